// round 16
// baseline (speedup 1.0000x reference)
#include <cuda_runtime.h>
#include <math.h>
#include <stdint.h>

#define NB    128
#define NPER  512
#define FIN   256
#define FOUT  256
#define NN    (NB * NPER)        // 65536
#define NE    (NN * 16)          // 1048576
#define KTOP  256
#define EPG   (NPER * 16)        // 8192 edges per graph

// ---------------- scratch (device globals; no allocations allowed) ----------
__device__ __align__(128) int   g_out_deg[NN];
__device__ __align__(128) int   g_in_deg[NN];
__device__ __align__(128) float g_src_norm[NN];
__device__ __align__(128) float g_dst_norm[NN];
__device__ __align__(128) int   g_csr_start[NN];
__device__ __align__(128) unsigned long long g_csr_pack[NE]; // lo: src local, hi: w bits
__device__ __align__(128) float g_h[(size_t)NN * FOUT];
__device__ __align__(128) float g_outf[(size_t)NN * FOUT];
__device__ __align__(128) float g_agg2[(size_t)NN * FOUT];
__device__ __align__(128) float g_score[NN];
__device__ __align__(128) int   g_perm[NB * KTOP];

#define DUP64(dst, f) asm("mov.b64 %0, {%1, %1};" : "=l"(dst) : "r"(__float_as_uint(f)))

// ---------------- prep kernels ----------------------------------------------
__global__ void k_zero() {
    int i = blockIdx.x * blockDim.x + threadIdx.x;
    if (i < NN) { g_out_deg[i] = 0; g_in_deg[i] = 0; }
}

__global__ void k_degree(const int* __restrict__ src, const int* __restrict__ dst) {
    int e = blockIdx.x * blockDim.x + threadIdx.x;
    if (e < NE) {
        atomicAdd(&g_out_deg[src[e]], 1);
        atomicAdd(&g_in_deg[dst[e]], 1);
    }
}

// norms: correctly-rounded n^-0.5 (libm powf path)
__global__ void k_norm() {
    int n = blockIdx.x * blockDim.x + threadIdx.x;
    if (n < NN) {
        double so = (double)max(g_out_deg[n], 1);
        double si = (double)max(g_in_deg[n], 1);
        g_src_norm[n] = (float)(1.0 / sqrt(so));
        g_dst_norm[n] = (float)(1.0 / sqrt(si));
    }
}

// ---------------- GEMM: h = (feat * src_norm) @ W ---------------------------
// fp32 packed fma.rn.f32x2, sequential ascending-k fma chain per output
// (bit-exact). Tile 128x64, 4x8 per thread, 3 CTAs/SM for stall cover.
#define BM 128
#define BN 64
#define BK 16
#define BMP (BM + 4)

__global__ __launch_bounds__(256, 3) void k_gemm(const float* __restrict__ feat,
                                                 const float* __restrict__ Wm) {
    __shared__ float  As[2][BK][BMP];     // ~16.9KB
    __shared__ float4 Bs4[2][BK][16];     // 8KB, permuted: cb -> ((cb&1)<<3)|(cb>>1)
    int tid = threadIdx.x;
    int ty = tid >> 3, tx = tid & 7;      // 32 row-groups x 8 col-groups
    int bm = blockIdx.x, bn = blockIdx.y;
    int row0 = bm * BM;

    unsigned long long acc[2][8];
#pragma unroll
    for (int p = 0; p < 2; p++)
#pragma unroll
        for (int j = 0; j < 8; j++) acc[p][j] = 0ull;

    const float4* f4 = (const float4*)feat;
    const float4* w4 = (const float4*)Wm;

    int ra  = tid >> 2, c4a = tid & 3;            // A staging (2 items)
    int ra2 = (tid + 256) >> 2, c4a2 = (tid + 256) & 3;
    int rb  = tid >> 4, cb = tid & 15;            // B staging (1 item)

    float4 pa[2], pb;
    float  psn[2];

    pa[0] = f4[(size_t)(row0 + ra)  * (FIN / 4) + c4a];
    pa[1] = f4[(size_t)(row0 + ra2) * (FIN / 4) + c4a2];
    psn[0] = g_src_norm[row0 + ra];
    psn[1] = g_src_norm[row0 + ra2];
    pb = w4[(size_t)rb * (FOUT / 4) + bn * (BN / 4) + cb];

    {
        int rr[2] = {ra, ra2}, cc[2] = {c4a, c4a2};
#pragma unroll
        for (int it = 0; it < 2; it++) {
            float sn = psn[it];
            As[0][cc[it] * 4 + 0][rr[it]] = __fmul_rn(pa[it].x, sn);
            As[0][cc[it] * 4 + 1][rr[it]] = __fmul_rn(pa[it].y, sn);
            As[0][cc[it] * 4 + 2][rr[it]] = __fmul_rn(pa[it].z, sn);
            As[0][cc[it] * 4 + 3][rr[it]] = __fmul_rn(pa[it].w, sn);
        }
        Bs4[0][rb][((cb & 1) << 3) | (cb >> 1)] = pb;
    }
    __syncthreads();

    int pbuf = 0;
    for (int k0 = 0; k0 < FIN; k0 += BK) {
        bool has_next = (k0 + BK < FIN);
        if (has_next) {
            pa[0] = f4[(size_t)(row0 + ra)  * (FIN / 4) + ((k0 + BK) >> 2) + c4a];
            pa[1] = f4[(size_t)(row0 + ra2) * (FIN / 4) + ((k0 + BK) >> 2) + c4a2];
            pb = w4[(size_t)(k0 + BK + rb) * (FOUT / 4) + bn * (BN / 4) + cb];
        }
#pragma unroll
        for (int kk = 0; kk < BK; kk++) {
            ulonglong2 a01 = *(const ulonglong2*)&As[pbuf][kk][ty * 4];
            unsigned long long ap[2] = {a01.x, a01.y};
            float4 q0 = Bs4[pbuf][kk][tx];        // cols 8tx+0..3
            float4 q1 = Bs4[pbuf][kk][8 + tx];    // cols 8tx+4..7
            unsigned long long bd[4];
            DUP64(bd[0], q0.x); DUP64(bd[1], q0.y);
            DUP64(bd[2], q0.z); DUP64(bd[3], q0.w);
#pragma unroll
            for (int p = 0; p < 2; p++)
#pragma unroll
                for (int j = 0; j < 4; j++)
                    asm("fma.rn.f32x2 %0, %1, %2, %0;"
                        : "+l"(acc[p][j]) : "l"(ap[p]), "l"(bd[j]));
            DUP64(bd[0], q1.x); DUP64(bd[1], q1.y);
            DUP64(bd[2], q1.z); DUP64(bd[3], q1.w);
#pragma unroll
            for (int p = 0; p < 2; p++)
#pragma unroll
                for (int j = 0; j < 4; j++)
                    asm("fma.rn.f32x2 %0, %1, %2, %0;"
                        : "+l"(acc[p][4 + j]) : "l"(ap[p]), "l"(bd[j]));
        }
        if (has_next) {
            int nb = pbuf ^ 1;
            int rr[2] = {ra, ra2}, cc[2] = {c4a, c4a2};
#pragma unroll
            for (int it = 0; it < 2; it++) {
                float sn = psn[it];
                As[nb][cc[it] * 4 + 0][rr[it]] = __fmul_rn(pa[it].x, sn);
                As[nb][cc[it] * 4 + 1][rr[it]] = __fmul_rn(pa[it].y, sn);
                As[nb][cc[it] * 4 + 2][rr[it]] = __fmul_rn(pa[it].z, sn);
                As[nb][cc[it] * 4 + 3][rr[it]] = __fmul_rn(pa[it].w, sn);
            }
            Bs4[nb][rb][((cb & 1) << 3) | (cb >> 1)] = pb;
            __syncthreads();
            pbuf = nb;
        }
    }

    // writeback: acc[p][j] = rows (ty*4+2p, +1), col bn*64 + tx*8 + j
#pragma unroll
    for (int p = 0; p < 2; p++) {
#pragma unroll
        for (int hh = 0; hh < 2; hh++) {
            int row = row0 + ty * 4 + 2 * p + hh;
            float v[8];
#pragma unroll
            for (int j = 0; j < 8; j++) {
                unsigned bits = hh ? (unsigned)(acc[p][j] >> 32)
                                   : (unsigned)(acc[p][j] & 0xFFFFFFFFull);
                v[j] = __uint_as_float(bits);
            }
            size_t base = (size_t)row * FOUT + bn * BN + tx * 8;
            *(float4*)&g_h[base]     = make_float4(v[0], v[1], v[2], v[3]);
            *(float4*)&g_h[base + 4] = make_float4(v[4], v[5], v[6], v[7]);
        }
    }
}

// STABLE CSR fill with fused per-graph scan. 512 threads per graph.
__global__ __launch_bounds__(512) void k_fill(const int* __restrict__ src,
                                              const int* __restrict__ dst,
                                              const float* __restrict__ ef) {
    __shared__ unsigned short hist[16][NPER];   // 16KB
    __shared__ int scan_s[NPER];                // 2KB
    __shared__ int start_s[NPER];               // 2KB
    int g = blockIdx.x;
    int tid = threadIdx.x;
    int w = tid >> 5, lane = tid & 31;
    int base = g * EPG;

    // fused exclusive scan of in-degree
    int cnt = g_in_deg[g * NPER + tid];
    scan_s[tid] = cnt;
    __syncthreads();
    for (int off = 1; off < NPER; off <<= 1) {
        int v = (tid >= off) ? scan_s[tid - off] : 0;
        __syncthreads();
        scan_s[tid] += v;
        __syncthreads();
    }
    int my_start = scan_s[tid] - cnt;           // graph-local exclusive
    start_s[tid] = my_start;
    g_csr_start[g * NPER + tid] = base + my_start;

    for (int i = tid; i < 16 * NPER; i += 512)
        ((unsigned short*)hist)[i] = 0;
    __syncthreads();

    for (int step = 0; step < 16; step++) {
        int e = base + w * 512 + step * 32 + lane;
        int d = dst[e] - g * NPER;
        unsigned mask = __match_any_sync(0xFFFFFFFFu, d);
        int leader = __ffs(mask) - 1;
        if (lane == leader) hist[w][d] = (unsigned short)(hist[w][d] + __popc(mask));
    }
    __syncthreads();

    {
        int c = 0;
        for (int ww = 0; ww < 16; ww++) {
            int t = hist[ww][tid];
            hist[ww][tid] = (unsigned short)c;
            c += t;
        }
    }
    __syncthreads();

    for (int step = 0; step < 16; step++) {
        int e = base + w * 512 + step * 32 + lane;
        int d = dst[e] - g * NPER;
        int s = src[e] - g * NPER;
        float wv = ef[e];
        unsigned mask = __match_any_sync(0xFFFFFFFFu, d);
        int leader = __ffs(mask) - 1;
        int rank = __popc(mask & ((1u << lane) - 1u));
        int b = 0;
        if (lane == leader) {
            b = hist[w][d];
            hist[w][d] = (unsigned short)(b + __popc(mask));
        }
        b = __shfl_sync(0xFFFFFFFFu, b, leader);
        int pos = base + start_s[d] + b + rank;
        g_csr_pack[pos] = ((unsigned long long)__float_as_uint(wv) << 32) | (unsigned)s;
    }
}

// ---------------- FUSED conv + agg2 (64-feature chunks, packed CSR) ---------
// smem: feat 512x64 (128KB) + packed edges (64KB) = 192KB. 512 threads.
// Dual-node chains (R13 form — empirically optimal). fp32 chains
// ascending-e (bit-exact); padded terms add exact zeros.
#define CONV_SMEM 196608
__global__ __launch_bounds__(512) void k_conv(const float* __restrict__ bias) {
    extern __shared__ float sh[];
    int g = blockIdx.x, ch = blockIdx.y;    // ch 0..3 (64 feats each)
    int tid = threadIdx.x;
    int lane = tid & 31, w = tid >> 5;      // 16 warps

    const float4* h4 = (const float4*)g_h;
    float4* s4 = (float4*)sh;
    for (int t = tid; t < NPER * 16; t += 512) {
        int r = t >> 4, c = t & 15;
        s4[t] = h4[(size_t)(g * NPER + r) * 64 + ch * 16 + c];
    }
    unsigned long long* pack = (unsigned long long*)(sh + NPER * 64);
    {
        const ulonglong2* cp2 = (const ulonglong2*)(g_csr_pack + (size_t)g * EPG);
        ulonglong2* dp2 = (ulonglong2*)pack;
        for (int t = tid; t < EPG / 2; t += 512) dp2[t] = cp2[t];
    }
    __syncthreads();

    int fb = ch * 64 + lane * 2;   // this lane's 2 features
    int fo = lane * 2;

    // Phase A: conv (dual-node)
    for (int nl = w; nl < NPER; nl += 32) {
        int nA = g * NPER + nl, nB = nA + 16;
        int stA = g_csr_start[nA] - g * EPG, cA = g_in_deg[nA];
        int stB = g_csr_start[nB] - g * EPG, cB = g_in_deg[nB];
        float ax = 0.f, ay = 0.f, bx = 0.f, by = 0.f;
        int m = max(cA, cB);
        for (int i = 0; i < m; i++) {
            int eA = (cA > 0) ? stA + min(i, cA - 1) : 0;
            int eB = (cB > 0) ? stB + min(i, cB - 1) : 0;
            unsigned long long pA = pack[eA], pB = pack[eB];
            int slA = (int)(pA & 0xFFFFu), slB = (int)(pB & 0xFFFFu);
            float wA = (i < cA) ? __uint_as_float((unsigned)(pA >> 32)) : 0.f;
            float wB = (i < cB) ? __uint_as_float((unsigned)(pB >> 32)) : 0.f;
            float2 fA = *(const float2*)&sh[slA * 64 + fo];
            float2 fB = *(const float2*)&sh[slB * 64 + fo];
            ax = __fadd_rn(ax, __fmul_rn(fA.x, wA));
            ay = __fadd_rn(ay, __fmul_rn(fA.y, wA));
            bx = __fadd_rn(bx, __fmul_rn(fB.x, wB));
            by = __fadd_rn(by, __fmul_rn(fB.y, wB));
        }
        float dnA = g_dst_norm[nA], dnB = g_dst_norm[nB];
        float2 bi = *(const float2*)&bias[fb];
        float2 oA, oB;
        oA.x = fmaxf(__fadd_rn(__fmul_rn(ax, dnA), bi.x), 0.f);
        oA.y = fmaxf(__fadd_rn(__fmul_rn(ay, dnA), bi.y), 0.f);
        oB.x = fmaxf(__fadd_rn(__fmul_rn(bx, dnB), bi.x), 0.f);
        oB.y = fmaxf(__fadd_rn(__fmul_rn(by, dnB), bi.y), 0.f);
        *(float2*)&g_outf[(size_t)nA * FOUT + fb] = oA;
        *(float2*)&g_outf[(size_t)nB * FOUT + fb] = oB;
    }
    __syncthreads();

    // Phase B: reload outf slab (CTA-coherent), scale by src_norm
    const float4* o4 = (const float4*)g_outf;
    for (int t = tid; t < NPER * 16; t += 512) {
        int r = t >> 4, c = t & 15;
        float sn = g_src_norm[g * NPER + r];
        float4 v = o4[(size_t)(g * NPER + r) * 64 + ch * 16 + c];
        v.x = __fmul_rn(v.x, sn); v.y = __fmul_rn(v.y, sn);
        v.z = __fmul_rn(v.z, sn); v.w = __fmul_rn(v.w, sn);
        s4[t] = v;
    }
    __syncthreads();

    // Phase C: agg2 (dual-node)
    for (int nl = w; nl < NPER; nl += 32) {
        int nA = g * NPER + nl, nB = nA + 16;
        int stA = g_csr_start[nA] - g * EPG, cA = g_in_deg[nA];
        int stB = g_csr_start[nB] - g * EPG, cB = g_in_deg[nB];
        float ax = 0.f, ay = 0.f, bx = 0.f, by = 0.f;
        int m = max(cA, cB);
        for (int i = 0; i < m; i++) {
            int eA = (cA > 0) ? stA + min(i, cA - 1) : 0;
            int eB = (cB > 0) ? stB + min(i, cB - 1) : 0;
            int slA = (int)(pack[eA] & 0xFFFFu);
            int slB = (int)(pack[eB] & 0xFFFFu);
            float2 fA = *(const float2*)&sh[slA * 64 + fo];
            float2 fB = *(const float2*)&sh[slB * 64 + fo];
            float vAx = (i < cA) ? fA.x : 0.f, vAy = (i < cA) ? fA.y : 0.f;
            float vBx = (i < cB) ? fB.x : 0.f, vBy = (i < cB) ? fB.y : 0.f;
            ax = __fadd_rn(ax, vAx); ay = __fadd_rn(ay, vAy);
            bx = __fadd_rn(bx, vBx); by = __fadd_rn(by, vBy);
        }
        *(float2*)&g_agg2[(size_t)nA * FOUT + fb] = make_float2(ax, ay);
        *(float2*)&g_agg2[(size_t)nB * FOUT + fb] = make_float2(bx, by);
    }
}

// ---------------- score = sum_f |out - agg2*dst_norm| -----------------------
// XLA:CPU EmitVectorizedReduce, VF=8: lane l sums f===l (mod 8) ascending;
// shards added lanewise then shuffle-halving.
__global__ void k_score_sum() {
    int tid = blockIdx.x * blockDim.x + threadIdx.x;
    int n = tid >> 3;                 // 8 lanes per node
    int j = tid & 7;
    if (n >= NN) return;
    float dn = g_dst_norm[n];
    const float* o = g_outf + (size_t)n * FOUT;
    const float* a = g_agg2 + (size_t)n * FOUT;
    float acc = 0.f;
#pragma unroll 4
    for (int i = 0; i < FOUT / 8; i++) {
        int f = j + 8 * i;
        float t = fabsf(__fsub_rn(o[f], __fmul_rn(a[f], dn)));
        acc = __fadd_rn(acc, t);
    }
    acc = __fadd_rn(acc, __shfl_down_sync(0xFFFFFFFFu, acc, 4));
    acc = __fadd_rn(acc, __shfl_down_sync(0xFFFFFFFFu, acc, 2));
    acc = __fadd_rn(acc, __shfl_down_sync(0xFFFFFFFFu, acc, 1));
    if (j == 0) g_score[n] = acc;
}

// ---------------- per-graph top-K via bitonic sort (desc score, asc idx) ----
__global__ void k_sort() {
    __shared__ float ss[NPER];
    __shared__ int   si[NPER];
    int g = blockIdx.x, tid = threadIdx.x;
    ss[tid] = g_score[g * NPER + tid];
    si[tid] = tid;
    __syncthreads();
    for (int k = 2; k <= NPER; k <<= 1) {
        for (int j = k >> 1; j > 0; j >>= 1) {
            int ixj = tid ^ j;
            if (ixj > tid) {
                float s1 = ss[tid], s2 = ss[ixj];
                int i1 = si[tid], i2 = si[ixj];
                bool before = (s1 > s2) || (s1 == s2 && i1 < i2);
                bool swap = ((tid & k) == 0) ? !before : before;
                if (swap) { ss[tid] = s2; ss[ixj] = s1; si[tid] = i2; si[ixj] = i1; }
            }
            __syncthreads();
        }
    }
    if (tid < KTOP) g_perm[g * KTOP + tid] = g * NPER + si[tid];
}

// ---------------- pooled gather (fully parallel, coalesced float4) ----------
__global__ void k_poolcopy(float* __restrict__ out) {
    int idx = blockIdx.x * 256 + threadIdx.x;   // float4 index
    int row = idx >> 6, c = idx & 63;           // row in [0, NB*KTOP)
    int g = row >> 8, j = row & 255;
    int p = g_perm[g * KTOP + j];
    ((float4*)out)[(size_t)row * 64 + c] = ((const float4*)g_outf)[(size_t)p * 64 + c];
}

// ---------------- readout (mean, max) over pooled (L2-hot) ------------------
__global__ void k_readout(float* __restrict__ out) {
    int g = blockIdx.x, f = threadIdx.x;   // 256 threads = 256 features
    const float* pooled = out;
    float* readout = out + (size_t)NB * KTOP * FOUT;
    float mx = -1e30f, sm = 0.f;
    for (int j = 0; j < KTOP; j++) {
        float v = pooled[((size_t)g * KTOP + j) * FOUT + f];
        sm = __fadd_rn(sm, v);
        mx = fmaxf(mx, v);
    }
    readout[(size_t)g * (2 * FOUT) + f]        = __fmul_rn(sm, 1.0f / KTOP);
    readout[(size_t)g * (2 * FOUT) + FOUT + f] = mx;
}

// ---------------- launch ----------------------------------------------------
extern "C" void kernel_launch(void* const* d_in, const int* in_sizes, int n_in,
                              void* d_out, int out_size) {
    const float* feat  = (const float*)d_in[0];
    const float* efeat = (const float*)d_in[1];
    const float* Wm    = (const float*)d_in[2];
    const float* bias  = (const float*)d_in[3];
    const int*   src   = (const int*)d_in[4];
    const int*   dst   = (const int*)d_in[5];
    float* out = (float*)d_out;

    cudaFuncSetAttribute(k_conv, cudaFuncAttributeMaxDynamicSharedMemorySize, CONV_SMEM);

    k_zero     <<<NN / 256, 256>>>();
    k_degree   <<<NE / 256, 256>>>(src, dst);
    k_norm     <<<NN / 256, 256>>>();
    k_gemm     <<<dim3(NN / BM, FOUT / BN), 256>>>(feat, Wm);
    k_fill     <<<NB, 512>>>(src, dst, efeat);
    k_conv     <<<dim3(NB, 4), 512, CONV_SMEM>>>(bias);
    k_score_sum<<<(NN * 8) / 256, 256>>>();
    k_sort     <<<NB, NPER>>>();
    k_poolcopy <<<(NB * KTOP * FOUT / 4) / 256, 256>>>(out);
    k_readout  <<<NB, 256>>>(out);
}

// round 17
// speedup vs baseline: 1.0529x; 1.0529x over previous
#include <cuda_runtime.h>
#include <math.h>
#include <stdint.h>

#define NB    128
#define NPER  512
#define FIN   256
#define FOUT  256
#define NN    (NB * NPER)        // 65536
#define NE    (NN * 16)          // 1048576
#define KTOP  256
#define EPG   (NPER * 16)        // 8192 edges per graph

// ---------------- scratch (device globals; no allocations allowed) ----------
__device__ __align__(128) int   g_out_deg[NN];
__device__ __align__(128) int   g_in_deg[NN];
__device__ __align__(128) float g_src_norm[NN];
__device__ __align__(128) float g_dst_norm[NN];
__device__ __align__(128) int   g_csr_start[NN];
__device__ __align__(128) unsigned long long g_csr_pack[NE]; // lo: src local, hi: w bits
__device__ __align__(128) float g_h[(size_t)NN * FOUT];
__device__ __align__(128) float g_outf[(size_t)NN * FOUT];
__device__ __align__(128) float g_agg2[(size_t)NN * FOUT];
__device__ __align__(128) float g_score[NN];
__device__ __align__(128) int   g_perm[NB * KTOP];

#define DUP64(dst, f) asm("mov.b64 %0, {%1, %1};" : "=l"(dst) : "r"(__float_as_uint(f)))

// ---------------- prep kernels ----------------------------------------------
__global__ void k_zero() {
    int i = blockIdx.x * blockDim.x + threadIdx.x;
    if (i < NN) { g_out_deg[i] = 0; g_in_deg[i] = 0; }
}

__global__ void k_degree(const int* __restrict__ src, const int* __restrict__ dst) {
    int e = blockIdx.x * blockDim.x + threadIdx.x;
    if (e < NE) {
        atomicAdd(&g_out_deg[src[e]], 1);
        atomicAdd(&g_in_deg[dst[e]], 1);
    }
}

// norms: correctly-rounded n^-0.5 (libm powf path)
__global__ void k_norm() {
    int n = blockIdx.x * blockDim.x + threadIdx.x;
    if (n < NN) {
        double so = (double)max(g_out_deg[n], 1);
        double si = (double)max(g_in_deg[n], 1);
        g_src_norm[n] = (float)(1.0 / sqrt(so));
        g_dst_norm[n] = (float)(1.0 / sqrt(si));
    }
}

// ---------------- GEMM: h = (feat * src_norm) @ W ---------------------------
// fp32 packed fma.rn.f32x2, sequential ascending-k fma chain per output.
// R13 configuration (empirically optimal): 128x128 tile, 8x8/thread,
// double-buffered smem, ONE sync per k-tile, 2 CTAs/SM.
#define BM 128
#define BN 128
#define BK 16
#define BMP (BM + 4)

__global__ __launch_bounds__(256, 2) void k_gemm(const float* __restrict__ feat,
                                                 const float* __restrict__ Wm) {
    __shared__ float  As[2][BK][BMP];
    __shared__ float4 Bs4[2][BK][32];   // permuted: c4 -> ((c4&1)<<4)|(c4>>1)
    int tid = threadIdx.x;
    int ty = tid >> 4, tx = tid & 15;
    int bm = blockIdx.x, bn = blockIdx.y;
    int row0 = bm * BM;

    unsigned long long acc[4][8];
#pragma unroll
    for (int p = 0; p < 4; p++)
#pragma unroll
        for (int j = 0; j < 8; j++) acc[p][j] = 0ull;

    const float4* f4 = (const float4*)feat;
    const float4* w4 = (const float4*)Wm;

    int ra  = tid >> 2, c4a = tid & 3;
    int ra2 = (tid + 256) >> 2, c4a2 = (tid + 256) & 3;
    int rb  = tid >> 5, cb = tid & 31;
    int rb2 = (tid + 256) >> 5, cb2 = (tid + 256) & 31;

    float4 pa[2], pb[2];
    float  psn[2];

    pa[0] = f4[(size_t)(row0 + ra)  * (FIN / 4) + c4a];
    pa[1] = f4[(size_t)(row0 + ra2) * (FIN / 4) + c4a2];
    psn[0] = g_src_norm[row0 + ra];
    psn[1] = g_src_norm[row0 + ra2];
    pb[0] = w4[(size_t)rb  * (FOUT / 4) + bn * (BN / 4) + cb];
    pb[1] = w4[(size_t)rb2 * (FOUT / 4) + bn * (BN / 4) + cb2];

    {
        int rr[2] = {ra, ra2}, cc[2] = {c4a, c4a2};
        int rrb[2] = {rb, rb2}, ccb[2] = {cb, cb2};
#pragma unroll
        for (int it = 0; it < 2; it++) {
            float sn = psn[it];
            As[0][cc[it] * 4 + 0][rr[it]] = __fmul_rn(pa[it].x, sn);
            As[0][cc[it] * 4 + 1][rr[it]] = __fmul_rn(pa[it].y, sn);
            As[0][cc[it] * 4 + 2][rr[it]] = __fmul_rn(pa[it].z, sn);
            As[0][cc[it] * 4 + 3][rr[it]] = __fmul_rn(pa[it].w, sn);
            Bs4[0][rrb[it]][((ccb[it] & 1) << 4) | (ccb[it] >> 1)] = pb[it];
        }
    }
    __syncthreads();

    int pbuf = 0;
    for (int k0 = 0; k0 < FIN; k0 += BK) {
        bool has_next = (k0 + BK < FIN);
        if (has_next) {
            pa[0] = f4[(size_t)(row0 + ra)  * (FIN / 4) + ((k0 + BK) >> 2) + c4a];
            pa[1] = f4[(size_t)(row0 + ra2) * (FIN / 4) + ((k0 + BK) >> 2) + c4a2];
            pb[0] = w4[(size_t)(k0 + BK + rb)  * (FOUT / 4) + bn * (BN / 4) + cb];
            pb[1] = w4[(size_t)(k0 + BK + rb2) * (FOUT / 4) + bn * (BN / 4) + cb2];
        }
#pragma unroll
        for (int kk = 0; kk < BK; kk++) {
            ulonglong2 a01 = *(const ulonglong2*)&As[pbuf][kk][ty * 8];
            ulonglong2 a23 = *(const ulonglong2*)&As[pbuf][kk][ty * 8 + 4];
            unsigned long long ap[4] = {a01.x, a01.y, a23.x, a23.y};
            float4 q0 = Bs4[pbuf][kk][tx];
            float4 q1 = Bs4[pbuf][kk][16 + tx];
            unsigned long long bd[8];
            DUP64(bd[0], q0.x); DUP64(bd[1], q0.y);
            DUP64(bd[2], q0.z); DUP64(bd[3], q0.w);
            DUP64(bd[4], q1.x); DUP64(bd[5], q1.y);
            DUP64(bd[6], q1.z); DUP64(bd[7], q1.w);
#pragma unroll
            for (int p = 0; p < 4; p++)
#pragma unroll
                for (int j = 0; j < 8; j++)
                    asm("fma.rn.f32x2 %0, %1, %2, %0;"
                        : "+l"(acc[p][j]) : "l"(ap[p]), "l"(bd[j]));
        }
        if (has_next) {
            int nb = pbuf ^ 1;
            int rr[2] = {ra, ra2}, cc[2] = {c4a, c4a2};
            int rrb[2] = {rb, rb2}, ccb[2] = {cb, cb2};
#pragma unroll
            for (int it = 0; it < 2; it++) {
                float sn = psn[it];
                As[nb][cc[it] * 4 + 0][rr[it]] = __fmul_rn(pa[it].x, sn);
                As[nb][cc[it] * 4 + 1][rr[it]] = __fmul_rn(pa[it].y, sn);
                As[nb][cc[it] * 4 + 2][rr[it]] = __fmul_rn(pa[it].z, sn);
                As[nb][cc[it] * 4 + 3][rr[it]] = __fmul_rn(pa[it].w, sn);
                Bs4[nb][rrb[it]][((ccb[it] & 1) << 4) | (ccb[it] >> 1)] = pb[it];
            }
            __syncthreads();
            pbuf = nb;
        }
    }

#pragma unroll
    for (int p = 0; p < 4; p++) {
#pragma unroll
        for (int hh = 0; hh < 2; hh++) {
            int row = row0 + ty * 8 + 2 * p + hh;
            float v[8];
#pragma unroll
            for (int j = 0; j < 8; j++) {
                unsigned bits = hh ? (unsigned)(acc[p][j] >> 32)
                                   : (unsigned)(acc[p][j] & 0xFFFFFFFFull);
                v[j] = __uint_as_float(bits);
            }
            size_t base = (size_t)row * FOUT + bn * BN + tx * 8;
            *(float4*)&g_h[base]     = make_float4(v[0], v[1], v[2], v[3]);
            *(float4*)&g_h[base + 4] = make_float4(v[4], v[5], v[6], v[7]);
        }
    }
}

// STABLE CSR fill with fused per-graph scan. 512 threads per graph.
__global__ __launch_bounds__(512) void k_fill(const int* __restrict__ src,
                                              const int* __restrict__ dst,
                                              const float* __restrict__ ef) {
    __shared__ unsigned short hist[16][NPER];   // 16KB
    __shared__ int scan_s[NPER];                // 2KB
    __shared__ int start_s[NPER];               // 2KB
    int g = blockIdx.x;
    int tid = threadIdx.x;
    int w = tid >> 5, lane = tid & 31;
    int base = g * EPG;

    // fused exclusive scan of in-degree
    int cnt = g_in_deg[g * NPER + tid];
    scan_s[tid] = cnt;
    __syncthreads();
    for (int off = 1; off < NPER; off <<= 1) {
        int v = (tid >= off) ? scan_s[tid - off] : 0;
        __syncthreads();
        scan_s[tid] += v;
        __syncthreads();
    }
    int my_start = scan_s[tid] - cnt;           // graph-local exclusive
    start_s[tid] = my_start;
    g_csr_start[g * NPER + tid] = base + my_start;

    for (int i = tid; i < 16 * NPER; i += 512)
        ((unsigned short*)hist)[i] = 0;
    __syncthreads();

    for (int step = 0; step < 16; step++) {
        int e = base + w * 512 + step * 32 + lane;
        int d = dst[e] - g * NPER;
        unsigned mask = __match_any_sync(0xFFFFFFFFu, d);
        int leader = __ffs(mask) - 1;
        if (lane == leader) hist[w][d] = (unsigned short)(hist[w][d] + __popc(mask));
    }
    __syncthreads();

    {
        int c = 0;
        for (int ww = 0; ww < 16; ww++) {
            int t = hist[ww][tid];
            hist[ww][tid] = (unsigned short)c;
            c += t;
        }
    }
    __syncthreads();

    for (int step = 0; step < 16; step++) {
        int e = base + w * 512 + step * 32 + lane;
        int d = dst[e] - g * NPER;
        int s = src[e] - g * NPER;
        float wv = ef[e];
        unsigned mask = __match_any_sync(0xFFFFFFFFu, d);
        int leader = __ffs(mask) - 1;
        int rank = __popc(mask & ((1u << lane) - 1u));
        int b = 0;
        if (lane == leader) {
            b = hist[w][d];
            hist[w][d] = (unsigned short)(b + __popc(mask));
        }
        b = __shfl_sync(0xFFFFFFFFu, b, leader);
        int pos = base + start_s[d] + b + rank;
        g_csr_pack[pos] = ((unsigned long long)__float_as_uint(wv) << 32) | (unsigned)s;
    }
}

// ---------------- FUSED conv + agg2 (64-feature chunks, packed CSR) ---------
// smem: feat 512x64 (128KB) + packed edges (64KB) = 192KB. 512 threads.
// Dual-node chains (R13 form — empirically optimal). fp32 chains
// ascending-e (bit-exact); padded terms add exact zeros.
#define CONV_SMEM 196608
__global__ __launch_bounds__(512) void k_conv(const float* __restrict__ bias) {
    extern __shared__ float sh[];
    int g = blockIdx.x, ch = blockIdx.y;    // ch 0..3 (64 feats each)
    int tid = threadIdx.x;
    int lane = tid & 31, w = tid >> 5;      // 16 warps

    const float4* h4 = (const float4*)g_h;
    float4* s4 = (float4*)sh;
    for (int t = tid; t < NPER * 16; t += 512) {
        int r = t >> 4, c = t & 15;
        s4[t] = h4[(size_t)(g * NPER + r) * 64 + ch * 16 + c];
    }
    unsigned long long* pack = (unsigned long long*)(sh + NPER * 64);
    {
        const ulonglong2* cp2 = (const ulonglong2*)(g_csr_pack + (size_t)g * EPG);
        ulonglong2* dp2 = (ulonglong2*)pack;
        for (int t = tid; t < EPG / 2; t += 512) dp2[t] = cp2[t];
    }
    __syncthreads();

    int fb = ch * 64 + lane * 2;   // this lane's 2 features
    int fo = lane * 2;

    // Phase A: conv (dual-node)
    for (int nl = w; nl < NPER; nl += 32) {
        int nA = g * NPER + nl, nB = nA + 16;
        int stA = g_csr_start[nA] - g * EPG, cA = g_in_deg[nA];
        int stB = g_csr_start[nB] - g * EPG, cB = g_in_deg[nB];
        float ax = 0.f, ay = 0.f, bx = 0.f, by = 0.f;
        int m = max(cA, cB);
        for (int i = 0; i < m; i++) {
            int eA = (cA > 0) ? stA + min(i, cA - 1) : 0;
            int eB = (cB > 0) ? stB + min(i, cB - 1) : 0;
            unsigned long long pA = pack[eA], pB = pack[eB];
            int slA = (int)(pA & 0xFFFFu), slB = (int)(pB & 0xFFFFu);
            float wA = (i < cA) ? __uint_as_float((unsigned)(pA >> 32)) : 0.f;
            float wB = (i < cB) ? __uint_as_float((unsigned)(pB >> 32)) : 0.f;
            float2 fA = *(const float2*)&sh[slA * 64 + fo];
            float2 fB = *(const float2*)&sh[slB * 64 + fo];
            ax = __fadd_rn(ax, __fmul_rn(fA.x, wA));
            ay = __fadd_rn(ay, __fmul_rn(fA.y, wA));
            bx = __fadd_rn(bx, __fmul_rn(fB.x, wB));
            by = __fadd_rn(by, __fmul_rn(fB.y, wB));
        }
        float dnA = g_dst_norm[nA], dnB = g_dst_norm[nB];
        float2 bi = *(const float2*)&bias[fb];
        float2 oA, oB;
        oA.x = fmaxf(__fadd_rn(__fmul_rn(ax, dnA), bi.x), 0.f);
        oA.y = fmaxf(__fadd_rn(__fmul_rn(ay, dnA), bi.y), 0.f);
        oB.x = fmaxf(__fadd_rn(__fmul_rn(bx, dnB), bi.x), 0.f);
        oB.y = fmaxf(__fadd_rn(__fmul_rn(by, dnB), bi.y), 0.f);
        *(float2*)&g_outf[(size_t)nA * FOUT + fb] = oA;
        *(float2*)&g_outf[(size_t)nB * FOUT + fb] = oB;
    }
    __syncthreads();

    // Phase B: reload outf slab (CTA-coherent), scale by src_norm
    const float4* o4 = (const float4*)g_outf;
    for (int t = tid; t < NPER * 16; t += 512) {
        int r = t >> 4, c = t & 15;
        float sn = g_src_norm[g * NPER + r];
        float4 v = o4[(size_t)(g * NPER + r) * 64 + ch * 16 + c];
        v.x = __fmul_rn(v.x, sn); v.y = __fmul_rn(v.y, sn);
        v.z = __fmul_rn(v.z, sn); v.w = __fmul_rn(v.w, sn);
        s4[t] = v;
    }
    __syncthreads();

    // Phase C: agg2 (dual-node)
    for (int nl = w; nl < NPER; nl += 32) {
        int nA = g * NPER + nl, nB = nA + 16;
        int stA = g_csr_start[nA] - g * EPG, cA = g_in_deg[nA];
        int stB = g_csr_start[nB] - g * EPG, cB = g_in_deg[nB];
        float ax = 0.f, ay = 0.f, bx = 0.f, by = 0.f;
        int m = max(cA, cB);
        for (int i = 0; i < m; i++) {
            int eA = (cA > 0) ? stA + min(i, cA - 1) : 0;
            int eB = (cB > 0) ? stB + min(i, cB - 1) : 0;
            int slA = (int)(pack[eA] & 0xFFFFu);
            int slB = (int)(pack[eB] & 0xFFFFu);
            float2 fA = *(const float2*)&sh[slA * 64 + fo];
            float2 fB = *(const float2*)&sh[slB * 64 + fo];
            float vAx = (i < cA) ? fA.x : 0.f, vAy = (i < cA) ? fA.y : 0.f;
            float vBx = (i < cB) ? fB.x : 0.f, vBy = (i < cB) ? fB.y : 0.f;
            ax = __fadd_rn(ax, vAx); ay = __fadd_rn(ay, vAy);
            bx = __fadd_rn(bx, vBx); by = __fadd_rn(by, vBy);
        }
        *(float2*)&g_agg2[(size_t)nA * FOUT + fb] = make_float2(ax, ay);
        *(float2*)&g_agg2[(size_t)nB * FOUT + fb] = make_float2(bx, by);
    }
}

// ---------------- score = sum_f |out - agg2*dst_norm| -----------------------
// XLA:CPU EmitVectorizedReduce, VF=8: lane l sums f===l (mod 8) ascending;
// shards added lanewise then shuffle-halving.
__global__ void k_score_sum() {
    int tid = blockIdx.x * blockDim.x + threadIdx.x;
    int n = tid >> 3;                 // 8 lanes per node
    int j = tid & 7;
    if (n >= NN) return;
    float dn = g_dst_norm[n];
    const float* o = g_outf + (size_t)n * FOUT;
    const float* a = g_agg2 + (size_t)n * FOUT;
    float acc = 0.f;
#pragma unroll 4
    for (int i = 0; i < FOUT / 8; i++) {
        int f = j + 8 * i;
        float t = fabsf(__fsub_rn(o[f], __fmul_rn(a[f], dn)));
        acc = __fadd_rn(acc, t);
    }
    acc = __fadd_rn(acc, __shfl_down_sync(0xFFFFFFFFu, acc, 4));
    acc = __fadd_rn(acc, __shfl_down_sync(0xFFFFFFFFu, acc, 2));
    acc = __fadd_rn(acc, __shfl_down_sync(0xFFFFFFFFu, acc, 1));
    if (j == 0) g_score[n] = acc;
}

// ---------------- per-graph top-K via bitonic sort (desc score, asc idx) ----
__global__ void k_sort() {
    __shared__ float ss[NPER];
    __shared__ int   si[NPER];
    int g = blockIdx.x, tid = threadIdx.x;
    ss[tid] = g_score[g * NPER + tid];
    si[tid] = tid;
    __syncthreads();
    for (int k = 2; k <= NPER; k <<= 1) {
        for (int j = k >> 1; j > 0; j >>= 1) {
            int ixj = tid ^ j;
            if (ixj > tid) {
                float s1 = ss[tid], s2 = ss[ixj];
                int i1 = si[tid], i2 = si[ixj];
                bool before = (s1 > s2) || (s1 == s2 && i1 < i2);
                bool swap = ((tid & k) == 0) ? !before : before;
                if (swap) { ss[tid] = s2; ss[ixj] = s1; si[tid] = i2; si[ixj] = i1; }
            }
            __syncthreads();
        }
    }
    if (tid < KTOP) g_perm[g * KTOP + tid] = g * NPER + si[tid];
}

// ---------------- pooled gather (fully parallel, coalesced float4) ----------
__global__ void k_poolcopy(float* __restrict__ out) {
    int idx = blockIdx.x * 256 + threadIdx.x;   // float4 index
    int row = idx >> 6, c = idx & 63;           // row in [0, NB*KTOP)
    int g = row >> 8, j = row & 255;
    int p = g_perm[g * KTOP + j];
    ((float4*)out)[(size_t)row * 64 + c] = ((const float4*)g_outf)[(size_t)p * 64 + c];
}

// ---------------- readout (mean, max) over pooled (L2-hot) ------------------
__global__ void k_readout(float* __restrict__ out) {
    int g = blockIdx.x, f = threadIdx.x;   // 256 threads = 256 features
    const float* pooled = out;
    float* readout = out + (size_t)NB * KTOP * FOUT;
    float mx = -1e30f, sm = 0.f;
    for (int j = 0; j < KTOP; j++) {
        float v = pooled[((size_t)g * KTOP + j) * FOUT + f];
        sm = __fadd_rn(sm, v);
        mx = fmaxf(mx, v);
    }
    readout[(size_t)g * (2 * FOUT) + f]        = __fmul_rn(sm, 1.0f / KTOP);
    readout[(size_t)g * (2 * FOUT) + FOUT + f] = mx;
}

// ---------------- launch ----------------------------------------------------
extern "C" void kernel_launch(void* const* d_in, const int* in_sizes, int n_in,
                              void* d_out, int out_size) {
    const float* feat  = (const float*)d_in[0];
    const float* efeat = (const float*)d_in[1];
    const float* Wm    = (const float*)d_in[2];
    const float* bias  = (const float*)d_in[3];
    const int*   src   = (const int*)d_in[4];
    const int*   dst   = (const int*)d_in[5];
    float* out = (float*)d_out;

    cudaFuncSetAttribute(k_conv, cudaFuncAttributeMaxDynamicSharedMemorySize, CONV_SMEM);

    k_zero     <<<NN / 256, 256>>>();
    k_degree   <<<NE / 256, 256>>>(src, dst);
    k_norm     <<<NN / 256, 256>>>();
    k_gemm     <<<dim3(NN / BM, FOUT / BN), 256>>>(feat, Wm);
    k_fill     <<<NB, 512>>>(src, dst, efeat);
    k_conv     <<<dim3(NB, 4), 512, CONV_SMEM>>>(bias);
    k_score_sum<<<(NN * 8) / 256, 256>>>();
    k_sort     <<<NB, NPER>>>();
    k_poolcopy <<<(NB * KTOP * FOUT / 4) / 256, 256>>>(out);
    k_readout  <<<NB, 256>>>(out);
}